// round 2
// baseline (speedup 1.0000x reference)
#include <cuda_runtime.h>
#include <math.h>
#include <stdint.h>

// Problem shape (fixed by setup_inputs)
#define Bc 4
#define Lc 4096
#define Dc 1024
#define Hc 2048
#define Mrows (Bc * Lc)            // 16384
#define BLD ((size_t)Mrows * Dc)   // 16,777,216

// ---------------------------------------------------------------------------
// Scratch: one big static device buffer, carved into regions (floats)
//   XN   : [16384,1024]                 @ 0
//   FRI  : [16384,2048] of float2       @ 16777216  (67,108,864 floats)
//   HBUF : [16384,2048]                 @ 83886080
//   X1   : [16384,1024]                 @ 117440512
//   XN2  : [16384,1024]                 @ 134217728
//   FF   : [16384,2048]                 @ 150994944
// total 184,549,376 floats = 738 MB
// ---------------------------------------------------------------------------
__device__ float g_buf[184549376];

#define OFF_XN   ((size_t)0)
#define OFF_FRI  ((size_t)16777216)
#define OFF_HBUF ((size_t)83886080)
#define OFF_X1   ((size_t)117440512)
#define OFF_XN2  ((size_t)134217728)
#define OFF_FF   ((size_t)150994944)

// ---------------------------------------------------------------------------
// RMSNorm: one block per row, 256 threads, D=1024 -> one float4 per thread
// ---------------------------------------------------------------------------
__global__ void __launch_bounds__(256) rmsnorm_kernel(
    const float* __restrict__ x, const float* __restrict__ g,
    float* __restrict__ out)
{
    const int row = blockIdx.x;
    const int t = threadIdx.x;
    const float4* xr = reinterpret_cast<const float4*>(x) + (size_t)row * (Dc / 4);
    float4 v = xr[t];
    float ss = v.x * v.x + v.y * v.y + v.z * v.z + v.w * v.w;
    #pragma unroll
    for (int off = 16; off > 0; off >>= 1)
        ss += __shfl_down_sync(0xffffffffu, ss, off);
    __shared__ float warp_s[8];
    if ((t & 31) == 0) warp_s[t >> 5] = ss;
    __syncthreads();
    float tot = 0.f;
    #pragma unroll
    for (int i = 0; i < 8; i++) tot += warp_s[i];
    const float scale = rsqrtf(tot * (1.0f / Dc) + 1e-6f);
    float4 gv = reinterpret_cast<const float4*>(g)[t];
    float4 o;
    o.x = v.x * scale * gv.x;
    o.y = v.y * scale * gv.y;
    o.z = v.z * scale * gv.z;
    o.w = v.w * scale * gv.w;
    (reinterpret_cast<float4*>(out) + (size_t)row * (Dc / 4))[t] = o;
}

// ---------------------------------------------------------------------------
// Tiled fp32 GEMM: C[M,N] = epilogue(A[M,K] @ W[N,K]^T)
// BM=BN=64, BK=16, 256 threads, 4x4 micro-tile per thread.
// MODE 0: dual weights -> write float2 { forget, remember*inp }  (N == H)
// MODE 1: dual weights -> ff = z1 * silu(z2)
// MODE 2: single weight -> z1 + bias + residual
// ---------------------------------------------------------------------------
__device__ __forceinline__ float sigmoidf_(float x) {
    return 1.0f / (1.0f + expf(-x));
}

template <int MODE>
__global__ void __launch_bounds__(256) gemm_kernel(
    const float* __restrict__ A,    // [M,K]
    const float* __restrict__ W1,   // [N,K]
    const float* __restrict__ W2,   // [N,K] (MODE 0/1) or unused
    const float* __restrict__ b1,   // [N]
    const float* __restrict__ b2,   // [N] (MODE 0/1) or unused
    const float* __restrict__ res,  // [M,N] (MODE 2) or unused
    float* __restrict__ out,        // MODE0: float2[M,N]; else float[M,N]
    int M, int N, int K)
{
    constexpr int NW2 = (MODE == 2) ? 1 : 16;
    __shared__ float As[16][68];    // [k][m], padded for float4-aligned rows
    __shared__ float W1s[16][68];
    __shared__ float W2s[NW2][68];

    const int tx = threadIdx.x & 15;   // 0..15 -> n
    const int ty = threadIdx.x >> 4;   // 0..15 -> m
    const int bm = blockIdx.y * 64;
    const int bn = blockIdx.x * 64;

    const int lrow = threadIdx.x >> 2; // 0..63
    const int lseg = threadIdx.x & 3;  // 0..3

    const float* Aptr  = A  + (size_t)(bm + lrow) * K + lseg * 4;
    const float* W1ptr = W1 + (size_t)(bn + lrow) * K + lseg * 4;
    const float* W2ptr = (MODE != 2) ? (W2 + (size_t)(bn + lrow) * K + lseg * 4) : A;

    float acc1[4][4] = {};
    float acc2[4][4] = {};

    for (int k0 = 0; k0 < K; k0 += 16) {
        float4 av  = *reinterpret_cast<const float4*>(Aptr + k0);
        float4 wv1 = *reinterpret_cast<const float4*>(W1ptr + k0);
        As[lseg * 4 + 0][lrow] = av.x;
        As[lseg * 4 + 1][lrow] = av.y;
        As[lseg * 4 + 2][lrow] = av.z;
        As[lseg * 4 + 3][lrow] = av.w;
        W1s[lseg * 4 + 0][lrow] = wv1.x;
        W1s[lseg * 4 + 1][lrow] = wv1.y;
        W1s[lseg * 4 + 2][lrow] = wv1.z;
        W1s[lseg * 4 + 3][lrow] = wv1.w;
        if (MODE != 2) {
            float4 wv2 = *reinterpret_cast<const float4*>(W2ptr + k0);
            W2s[(lseg * 4 + 0) % NW2][lrow] = wv2.x;
            W2s[(lseg * 4 + 1) % NW2][lrow] = wv2.y;
            W2s[(lseg * 4 + 2) % NW2][lrow] = wv2.z;
            W2s[(lseg * 4 + 3) % NW2][lrow] = wv2.w;
        }
        __syncthreads();

        #pragma unroll
        for (int kk = 0; kk < 16; kk++) {
            float4 a4 = *reinterpret_cast<const float4*>(&As[kk][ty * 4]);
            float4 w4 = *reinterpret_cast<const float4*>(&W1s[kk][tx * 4]);
            float aa[4] = {a4.x, a4.y, a4.z, a4.w};
            float ww[4] = {w4.x, w4.y, w4.z, w4.w};
            float w2a[4];
            if (MODE != 2) {
                float4 w24 = *reinterpret_cast<const float4*>(&W2s[kk % NW2][tx * 4]);
                w2a[0] = w24.x; w2a[1] = w24.y; w2a[2] = w24.z; w2a[3] = w24.w;
            }
            #pragma unroll
            for (int i = 0; i < 4; i++) {
                #pragma unroll
                for (int j = 0; j < 4; j++) {
                    acc1[i][j] = fmaf(aa[i], ww[j], acc1[i][j]);
                    if (MODE != 2) acc2[i][j] = fmaf(aa[i], w2a[j], acc2[i][j]);
                }
            }
        }
        __syncthreads();
    }

    // Epilogue
    #pragma unroll
    for (int j = 0; j < 4; j++) {
        const int gn = bn + tx * 4 + j;
        const float bias1 = b1[gn];
        float bias2 = 0.f, decay = 0.f;
        if (MODE != 2) bias2 = b2[gn];
        if (MODE == 0) decay = (float)gn / (float)(N - 1);
        #pragma unroll
        for (int i = 0; i < 4; i++) {
            const int gm = bm + ty * 4 + i;
            const size_t idx = (size_t)gm * N + gn;
            const float z1 = acc1[i][j] + bias1;
            if (MODE == 0) {
                const float z2 = acc2[i][j] + bias2;
                const float rem = decay * sigmoidf_(z1);
                float2 fr;
                fr.x = 1.0f - rem;          // forget
                fr.y = rem * tanhf(z2);     // remember * inp
                reinterpret_cast<float2*>(out)[idx] = fr;
            } else if (MODE == 1) {
                const float z2 = acc2[i][j] + bias2;
                out[idx] = z1 * (z2 * sigmoidf_(z2));   // fc * silu(fc_act)
            } else {
                out[idx] = z1 + res[idx];
            }
        }
    }
}

// ---------------------------------------------------------------------------
// Inclusive linear recurrence: carry = f*carry + ri over L, per (b,h) channel.
// carry initialized with hidden[b,h] (folds in hidden * cumprod(forget)).
// ---------------------------------------------------------------------------
__global__ void __launch_bounds__(256) scan_kernel(
    const float2* __restrict__ fri,   // [B, L, H] interleaved (f, r*i)
    const float* __restrict__ hidden, // [B, H]
    float* __restrict__ hbuf,         // [B, L, H]
    float* __restrict__ hlast)        // [B, H]
{
    const int idx = blockIdx.x * blockDim.x + threadIdx.x;  // 0 .. B*H-1
    const int b = idx / Hc;
    const int h = idx - b * Hc;
    float carry = hidden[idx];
    const float2* p = fri + (size_t)b * Lc * Hc + h;
    float* o = hbuf + (size_t)b * Lc * Hc + h;
    for (int t = 0; t < Lc; t += 8) {
        float2 v[8];
        #pragma unroll
        for (int u = 0; u < 8; u++) v[u] = p[(size_t)(t + u) * Hc];
        #pragma unroll
        for (int u = 0; u < 8; u++) {
            carry = fmaf(v[u].x, carry, v[u].y);
            o[(size_t)(t + u) * Hc] = carry;
        }
    }
    hlast[idx] = carry;
}

// ---------------------------------------------------------------------------
// kernel_launch
// inputs: 0:x 1:hidden 2:w_forget 3:b_forget 4:w_input 5:b_input 6:w_hout
//         7:b_hout 8:w_fc 9:b_fc 10:w_fc_act 11:b_fc_act 12:w_fout 13:b_fout
//         14:g_norm1 15:g_norm2
// output: [ out (B,L,D) | h_last (B,H) ] fp32
// ---------------------------------------------------------------------------
extern "C" void kernel_launch(void* const* d_in, const int* in_sizes, int n_in,
                              void* d_out, int out_size)
{
    const float* x        = (const float*)d_in[0];
    const float* hidden   = (const float*)d_in[1];
    const float* w_forget = (const float*)d_in[2];
    const float* b_forget = (const float*)d_in[3];
    const float* w_input  = (const float*)d_in[4];
    const float* b_input  = (const float*)d_in[5];
    const float* w_hout   = (const float*)d_in[6];
    const float* b_hout   = (const float*)d_in[7];
    const float* w_fc     = (const float*)d_in[8];
    const float* b_fc     = (const float*)d_in[9];
    const float* w_fc_act = (const float*)d_in[10];
    const float* b_fc_act = (const float*)d_in[11];
    const float* w_fout   = (const float*)d_in[12];
    const float* b_fout   = (const float*)d_in[13];
    const float* g_norm1  = (const float*)d_in[14];
    const float* g_norm2  = (const float*)d_in[15];
    float* out = (float*)d_out;

    float* gbuf = nullptr;
    cudaGetSymbolAddress((void**)&gbuf, g_buf);
    float* XN   = gbuf + OFF_XN;
    float* FRI  = gbuf + OFF_FRI;   // float2 region
    float* HBUF = gbuf + OFF_HBUF;
    float* X1   = gbuf + OFF_X1;
    float* XN2  = gbuf + OFF_XN2;
    float* FF   = gbuf + OFF_FF;

    // 1. xn = rmsnorm(x) * g1
    rmsnorm_kernel<<<Mrows, 256>>>(x, g_norm1, XN);

    // 2. dual GEMM -> (forget, remember*inp) interleaved
    gemm_kernel<0><<<dim3(Hc / 64, Mrows / 64), 256>>>(
        XN, w_forget, w_input, b_forget, b_input, nullptr, FRI,
        Mrows, Hc, Dc);

    // 3. recurrence scan; also emits h_last into output tail
    scan_kernel<<<(Bc * Hc) / 256, 256>>>(
        (const float2*)FRI, hidden, HBUF, out + BLD);

    // 4. x1 = h @ w_hout^T + b_hout + x
    gemm_kernel<2><<<dim3(Dc / 64, Mrows / 64), 256>>>(
        HBUF, w_hout, nullptr, b_hout, nullptr, x, X1,
        Mrows, Dc, Hc);

    // 5. xn2 = rmsnorm(x1) * g2
    rmsnorm_kernel<<<Mrows, 256>>>(X1, g_norm2, XN2);

    // 6. dual GEMM -> ff = fc * silu(fc_act)
    gemm_kernel<1><<<dim3(Hc / 64, Mrows / 64), 256>>>(
        XN2, w_fc, w_fc_act, b_fc, b_fc_act, nullptr, FF,
        Mrows, Hc, Dc);

    // 7. out = ff @ w_fout^T + b_fout + x1
    gemm_kernel<2><<<dim3(Dc / 64, Mrows / 64), 256>>>(
        FF, w_fout, nullptr, b_fout, nullptr, X1, out,
        Mrows, Dc, Hc);

    (void)in_sizes; (void)n_in; (void)out_size;
}

// round 4
// speedup vs baseline: 3.4233x; 3.4233x over previous
#include <cuda_runtime.h>
#include <math.h>
#include <stdint.h>

// Problem shape (fixed by setup_inputs)
#define Bc 4
#define Lc 4096
#define Dc 1024
#define Hc 2048
#define Mrows (Bc * Lc)            // 16384
#define BLD ((size_t)Mrows * Dc)   // 16,777,216

// ---------------------------------------------------------------------------
// Scratch regions (floats)
// ---------------------------------------------------------------------------
__device__ float g_buf[197132288];

#define OFF_XN   ((size_t)0)
#define OFF_FRI  ((size_t)16777216)     // float2 [16384,2048]
#define OFF_HBUF ((size_t)83886080)
#define OFF_X1   ((size_t)117440512)
#define OFF_XN2  ((size_t)134217728)
#define OFF_FF   ((size_t)150994944)
#define OFF_WT   ((size_t)184549376)    // 6 x 2,097,152 tf32 weights

#define WSEG ((size_t)2097152)

// ---------------------------------------------------------------------------
// helpers
// ---------------------------------------------------------------------------
__device__ __forceinline__ float to_tf32(float x) {
    uint32_t u;
    asm("cvt.rna.tf32.f32 %0, %1;" : "=r"(u) : "f"(x));
    return __uint_as_float(u);
}

__device__ __forceinline__ float sigmoidf_(float x) {
    return 1.0f / (1.0f + expf(-x));
}

__device__ __forceinline__ void cp16(float* dst, const float* src) {
    uint32_t d = (uint32_t)__cvta_generic_to_shared(dst);
    asm volatile("cp.async.cg.shared.global [%0], [%1], 16;\n" :: "r"(d), "l"(src));
}

__device__ __forceinline__ void mma_tf32(float4& c, float2 alo, float2 ahi, float2 b) {
    // slot-k permutation: (a0,a2) = alo.{x,y}; (a1,a3) = ahi.{x,y}; (b0,b1) = b.{x,y}
    asm volatile(
        "mma.sync.aligned.m16n8k8.row.col.f32.tf32.tf32.f32 "
        "{%0,%1,%2,%3}, {%4,%5,%6,%7}, {%8,%9}, {%0,%1,%2,%3};\n"
        : "+f"(c.x), "+f"(c.y), "+f"(c.z), "+f"(c.w)
        : "r"(__float_as_uint(alo.x)), "r"(__float_as_uint(ahi.x)),
          "r"(__float_as_uint(alo.y)), "r"(__float_as_uint(ahi.y)),
          "r"(__float_as_uint(b.x)),  "r"(__float_as_uint(b.y)));
}

// ---------------------------------------------------------------------------
// Weight prep: fp32 -> tf32(RN) copies of all 6 weight matrices (each 2M elems)
// ---------------------------------------------------------------------------
__global__ void __launch_bounds__(256) prep_weights(
    const float* __restrict__ w0, const float* __restrict__ w1,
    const float* __restrict__ w2, const float* __restrict__ w3,
    const float* __restrict__ w4, const float* __restrict__ w5,
    float* __restrict__ dst)
{
    const size_t i4 = (size_t)blockIdx.x * 256 + threadIdx.x;   // float4 index
    const int seg = (int)(i4 >> 19);            // 524288 float4 per matrix
    const size_t off = (i4 & 524287) * 4;
    const float* src;
    switch (seg) {
        case 0: src = w0; break; case 1: src = w1; break;
        case 2: src = w2; break; case 3: src = w3; break;
        case 4: src = w4; break; default: src = w5; break;
    }
    float4 v = *reinterpret_cast<const float4*>(src + off);
    v.x = to_tf32(v.x); v.y = to_tf32(v.y);
    v.z = to_tf32(v.z); v.w = to_tf32(v.w);
    *reinterpret_cast<float4*>(dst + seg * WSEG + off) = v;
}

// ---------------------------------------------------------------------------
// RMSNorm: one block per row, 256 threads, D=1024; output rounded to tf32
// ---------------------------------------------------------------------------
__global__ void __launch_bounds__(256) rmsnorm_kernel(
    const float* __restrict__ x, const float* __restrict__ g,
    float* __restrict__ out)
{
    const int row = blockIdx.x;
    const int t = threadIdx.x;
    const float4* xr = reinterpret_cast<const float4*>(x) + (size_t)row * (Dc / 4);
    float4 v = xr[t];
    float ss = v.x * v.x + v.y * v.y + v.z * v.z + v.w * v.w;
    #pragma unroll
    for (int off = 16; off > 0; off >>= 1)
        ss += __shfl_down_sync(0xffffffffu, ss, off);
    __shared__ float warp_s[8];
    if ((t & 31) == 0) warp_s[t >> 5] = ss;
    __syncthreads();
    float tot = 0.f;
    #pragma unroll
    for (int i = 0; i < 8; i++) tot += warp_s[i];
    const float scale = rsqrtf(tot * (1.0f / Dc) + 1e-6f);
    float4 gv = reinterpret_cast<const float4*>(g)[t];
    float4 o;
    o.x = to_tf32(v.x * scale * gv.x);
    o.y = to_tf32(v.y * scale * gv.y);
    o.z = to_tf32(v.z * scale * gv.z);
    o.w = to_tf32(v.w * scale * gv.w);
    (reinterpret_cast<float4*>(out) + (size_t)row * (Dc / 4))[t] = o;
}

// ---------------------------------------------------------------------------
// Tensor-core tf32 GEMM: C[M,N] = epilogue(A[M,K] @ W[N,K]^T)
// BM=128, BN=64, BK=32, 256 threads (8 warps: 4m x 2n), warp tile 32x32.
// m16n8k8 tf32 HMMA with k-slot permutation so all fragment loads are LDS.64.
// Smem row stride = 40 floats (20 float2, ≡4 mod 16 -> conflict-free frags).
// 2-stage cp.async pipeline. Dynamic smem = 2 * 10240 floats = 80 KB.
// MODE 0: dual -> float2 { forget, remember*inp }
// MODE 1: dual -> ff = tf32( z1 * silu(z2) )
// MODE 2: single -> z1 + bias + residual
// ---------------------------------------------------------------------------
template <int MODE>
__global__ void __launch_bounds__(256, 2) gemm_tc(
    const float* __restrict__ A,
    const float* __restrict__ W1,
    const float* __restrict__ W2,
    const float* __restrict__ b1,
    const float* __restrict__ b2,
    const float* __restrict__ res,
    float* __restrict__ out,
    int M, int N, int K)
{
    constexpr bool DUAL = (MODE != 2);
    extern __shared__ float sm[];

    const int tid  = threadIdx.x;
    const int lane = tid & 31;
    const int warp = tid >> 5;
    const int wm = warp >> 1;          // 0..3
    const int wn = warp & 1;           // 0..1
    const int gid = lane >> 2;         // 0..7
    const int tig = lane & 3;          // 0..3
    const int bm = blockIdx.y * 128;
    const int bn = blockIdx.x * 64;
    const int niter = K >> 5;

    float4 acc1[2][4];
    float4 acc2[2][4];
    #pragma unroll
    for (int i = 0; i < 2; i++)
        #pragma unroll
        for (int j = 0; j < 4; j++) {
            acc1[i][j] = make_float4(0.f, 0.f, 0.f, 0.f);
            acc2[i][j] = make_float4(0.f, 0.f, 0.f, 0.f);
        }

    auto load_stage = [&](int buf, int k0) {
        float* s = sm + buf * 10240;
        #pragma unroll
        for (int i = 0; i < 4; i++) {
            int q = tid + 256 * i;
            int row = q >> 3, c = q & 7;
            cp16(s + row * 40 + c * 4, A + (size_t)(bm + row) * K + k0 + c * 4);
        }
        #pragma unroll
        for (int i = 0; i < 2; i++) {
            int q = tid + 256 * i;
            int row = q >> 3, c = q & 7;
            cp16(s + 5120 + row * 40 + c * 4, W1 + (size_t)(bn + row) * K + k0 + c * 4);
            if (DUAL)
                cp16(s + 7680 + row * 40 + c * 4, W2 + (size_t)(bn + row) * K + k0 + c * 4);
        }
    };

    load_stage(0, 0);
    asm volatile("cp.async.commit_group;\n");

    for (int it = 0; it < niter; it++) {
        if (it + 1 < niter)
            load_stage((it + 1) & 1, (it + 1) << 5);
        asm volatile("cp.async.commit_group;\n");
        asm volatile("cp.async.wait_group 1;\n");
        __syncthreads();

        const float* buf = sm + (it & 1) * 10240;
        const float2* Af = reinterpret_cast<const float2*>(buf);
        const float2* B1f = reinterpret_cast<const float2*>(buf + 5120);
        const float2* B2f = reinterpret_cast<const float2*>(buf + 7680);

        #pragma unroll
        for (int s = 0; s < 4; s++) {
            float2 alo[2], ahi[2];
            #pragma unroll
            for (int mf = 0; mf < 2; mf++) {
                const int r = wm * 32 + mf * 16 + gid;
                alo[mf] = Af[r * 20 + s * 4 + tig];
                ahi[mf] = Af[(r + 8) * 20 + s * 4 + tig];
            }
            #pragma unroll
            for (int nf = 0; nf < 4; nf++) {
                const int n = wn * 32 + nf * 8 + gid;
                const float2 bv = B1f[n * 20 + s * 4 + tig];
                float2 cv;
                if (DUAL) cv = B2f[n * 20 + s * 4 + tig];
                #pragma unroll
                for (int mf = 0; mf < 2; mf++) {
                    mma_tf32(acc1[mf][nf], alo[mf], ahi[mf], bv);
                    if (DUAL) mma_tf32(acc2[mf][nf], alo[mf], ahi[mf], cv);
                }
            }
        }
        __syncthreads();
    }

    // ------------------------------ Epilogue ------------------------------
    #pragma unroll
    for (int nf = 0; nf < 4; nf++) {
        const int c0 = bn + wn * 32 + nf * 8 + 2 * tig;   // even
        const float bias1a = b1[c0], bias1b = b1[c0 + 1];
        float bias2a = 0.f, bias2b = 0.f;
        if (DUAL) { bias2a = b2[c0]; bias2b = b2[c0 + 1]; }
        float decaya = 0.f, decayb = 0.f;
        if (MODE == 0) {
            decaya = (float)c0 / (float)(N - 1);
            decayb = (float)(c0 + 1) / (float)(N - 1);
        }
        #pragma unroll
        for (int mf = 0; mf < 2; mf++) {
            const int r0 = bm + wm * 32 + mf * 16 + gid;
            const float4 a1 = acc1[mf][nf];
            const float4 a2 = acc2[mf][nf];
            // rows r0 (a.x,a.y) and r0+8 (a.z,a.w)
            #pragma unroll
            for (int h = 0; h < 2; h++) {
                const int r = r0 + h * 8;
                const float z1a = (h ? a1.z : a1.x) + bias1a;
                const float z1b = (h ? a1.w : a1.y) + bias1b;
                const size_t idx = (size_t)r * N + c0;
                if (MODE == 0) {
                    const float z2a = (h ? a2.z : a2.x) + bias2a;
                    const float z2b = (h ? a2.w : a2.y) + bias2b;
                    const float rema = decaya * sigmoidf_(z1a);
                    const float remb = decayb * sigmoidf_(z1b);
                    float4 o;
                    o.x = 1.0f - rema;  o.y = rema * tanhf(z2a);
                    o.z = 1.0f - remb;  o.w = remb * tanhf(z2b);
                    *reinterpret_cast<float4*>(reinterpret_cast<float2*>(out) + idx) = o;
                } else if (MODE == 1) {
                    const float z2a = (h ? a2.z : a2.x) + bias2a;
                    const float z2b = (h ? a2.w : a2.y) + bias2b;
                    float2 o;
                    o.x = to_tf32(z1a * (z2a * sigmoidf_(z2a)));
                    o.y = to_tf32(z1b * (z2b * sigmoidf_(z2b)));
                    *reinterpret_cast<float2*>(out + idx) = o;
                } else {
                    const float2 rv = *reinterpret_cast<const float2*>(res + idx);
                    float2 o;
                    o.x = z1a + rv.x;
                    o.y = z1b + rv.y;
                    *reinterpret_cast<float2*>(out + idx) = o;
                }
            }
        }
    }
    (void)M;
}

// ---------------------------------------------------------------------------
// Inclusive linear recurrence per (b,h): carry = f*carry + ri.
// HBUF stores rounded to tf32 (it feeds the next GEMM); carry stays fp32.
// ---------------------------------------------------------------------------
__global__ void __launch_bounds__(256) scan_kernel(
    const float2* __restrict__ fri,
    const float* __restrict__ hidden,
    float* __restrict__ hbuf,
    float* __restrict__ hlast)
{
    const int idx = blockIdx.x * blockDim.x + threadIdx.x;
    const int b = idx / Hc;
    const int h = idx - b * Hc;
    float carry = hidden[idx];
    const float2* p = fri + (size_t)b * Lc * Hc + h;
    float* o = hbuf + (size_t)b * Lc * Hc + h;
    for (int t = 0; t < Lc; t += 8) {
        float2 v[8];
        #pragma unroll
        for (int u = 0; u < 8; u++) v[u] = p[(size_t)(t + u) * Hc];
        #pragma unroll
        for (int u = 0; u < 8; u++) {
            carry = fmaf(v[u].x, carry, v[u].y);
            o[(size_t)(t + u) * Hc] = to_tf32(carry);
        }
    }
    hlast[idx] = carry;
}

// ---------------------------------------------------------------------------
// kernel_launch
// ---------------------------------------------------------------------------
extern "C" void kernel_launch(void* const* d_in, const int* in_sizes, int n_in,
                              void* d_out, int out_size)
{
    const float* x        = (const float*)d_in[0];
    const float* hidden   = (const float*)d_in[1];
    const float* w_forget = (const float*)d_in[2];
    const float* b_forget = (const float*)d_in[3];
    const float* w_input  = (const float*)d_in[4];
    const float* b_input  = (const float*)d_in[5];
    const float* w_hout   = (const float*)d_in[6];
    const float* b_hout   = (const float*)d_in[7];
    const float* w_fc     = (const float*)d_in[8];
    const float* b_fc     = (const float*)d_in[9];
    const float* w_fc_act = (const float*)d_in[10];
    const float* b_fc_act = (const float*)d_in[11];
    const float* w_fout   = (const float*)d_in[12];
    const float* b_fout   = (const float*)d_in[13];
    const float* g_norm1  = (const float*)d_in[14];
    const float* g_norm2  = (const float*)d_in[15];
    float* out = (float*)d_out;

    float* gbuf = nullptr;
    cudaGetSymbolAddress((void**)&gbuf, g_buf);
    float* XN   = gbuf + OFF_XN;
    float* FRI  = gbuf + OFF_FRI;
    float* HBUF = gbuf + OFF_HBUF;
    float* X1   = gbuf + OFF_X1;
    float* XN2  = gbuf + OFF_XN2;
    float* FF   = gbuf + OFF_FF;
    float* WT   = gbuf + OFF_WT;

    const int smem = 2 * 10240 * 4;   // 80 KB
    static bool attr_done = false;
    if (!attr_done) {
        cudaFuncSetAttribute(gemm_tc<0>, cudaFuncAttributeMaxDynamicSharedMemorySize, smem);
        cudaFuncSetAttribute(gemm_tc<1>, cudaFuncAttributeMaxDynamicSharedMemorySize, smem);
        cudaFuncSetAttribute(gemm_tc<2>, cudaFuncAttributeMaxDynamicSharedMemorySize, smem);
        attr_done = true;
    }

    // 0. tf32-round all weights into scratch
    prep_weights<<<12288, 256>>>(w_forget, w_input, w_hout, w_fc, w_fc_act, w_fout, WT);
    const float* Wf   = WT + 0 * WSEG;
    const float* Wi   = WT + 1 * WSEG;
    const float* Who  = WT + 2 * WSEG;
    const float* Wfc  = WT + 3 * WSEG;
    const float* Wfca = WT + 4 * WSEG;
    const float* Wfo  = WT + 5 * WSEG;

    // 1. xn = tf32(rmsnorm(x) * g1)
    rmsnorm_kernel<<<Mrows, 256>>>(x, g_norm1, XN);

    // 2. dual GEMM -> (forget, remember*inp)
    gemm_tc<0><<<dim3(Hc / 64, Mrows / 128), 256, smem>>>(
        XN, Wf, Wi, b_forget, b_input, nullptr, FRI, Mrows, Hc, Dc);

    // 3. recurrence scan (emits h_last to output tail)
    scan_kernel<<<(Bc * Hc) / 256, 256>>>((const float2*)FRI, hidden, HBUF, out + BLD);

    // 4. x1 = h @ w_hout^T + b_hout + x
    gemm_tc<2><<<dim3(Dc / 64, Mrows / 128), 256, smem>>>(
        HBUF, Who, nullptr, b_hout, nullptr, x, X1, Mrows, Dc, Hc);

    // 5. xn2 = tf32(rmsnorm(x1) * g2)
    rmsnorm_kernel<<<Mrows, 256>>>(X1, g_norm2, XN2);

    // 6. dual GEMM -> ff = fc * silu(fc_act)
    gemm_tc<1><<<dim3(Hc / 64, Mrows / 128), 256, smem>>>(
        XN2, Wfc, Wfca, b_fc, b_fc_act, nullptr, FF, Mrows, Hc, Dc);

    // 7. out = ff @ w_fout^T + b_fout + x1
    gemm_tc<2><<<dim3(Dc / 64, Mrows / 128), 256, smem>>>(
        FF, Wfo, nullptr, b_fout, nullptr, X1, out, Mrows, Dc, Hc);

    (void)in_sizes; (void)n_in; (void)out_size;
}

// round 7
// speedup vs baseline: 6.1777x; 1.8046x over previous
#include <cuda_runtime.h>
#include <cuda_fp16.h>
#include <math.h>
#include <stdint.h>

// Problem shape (fixed by setup_inputs)
#define Bc 4
#define Lc 4096
#define Dc 1024
#define Hc 2048
#define Mrows (Bc * Lc)            // 16384
#define BLD ((size_t)Mrows * Dc)   // 16,777,216

// ---------------------------------------------------------------------------
// Scratch regions (float units)  — FIXED layout (FRI is 67,108,864 floats!)
//   FRI  float2 [16384,2048]            @ 0          (67,108,864 floats)
//   HBUF half   [16384,2048] permuted   @ 67108864   (16,777,216 floats)
//   X1   float  [16384,1024]            @ 83886080   (16,777,216 floats)
//   XN   half   [16384,1024] permuted   @ 100663296  ( 8,388,608 floats)
//   XN2  half   [16384,1024] permuted   @ 109051904  ( 8,388,608 floats)
//   FF   half   [16384,2048] permuted   @ 117440512  (16,777,216 floats)
//   WT   half   6 x 2,097,152 permuted  @ 134217728  ( 6,291,456 floats)
//   AB   float2 [4*64*2048]             @ 140509184  ( 1,048,576 floats)
//   CIN  float  [4*64*2048]             @ 141557760  (   524,288 floats)
// total 142,082,048 floats = 568 MB
// ---------------------------------------------------------------------------
__device__ float g_buf[142082048];

#define OFF_FRI  ((size_t)0)
#define OFF_HBUF ((size_t)67108864)
#define OFF_X1   ((size_t)83886080)
#define OFF_XN   ((size_t)100663296)
#define OFF_XN2  ((size_t)109051904)
#define OFF_FF   ((size_t)117440512)
#define OFF_WT   ((size_t)134217728)
#define OFF_AB   ((size_t)140509184)
#define OFF_CIN  ((size_t)141557760)

#define WSEG_H ((size_t)2097152)   // halfs per weight matrix

// ---------------------------------------------------------------------------
// helpers
// ---------------------------------------------------------------------------
__device__ __forceinline__ float sigmoidf_(float x) {
    return 1.0f / (1.0f + expf(-x));
}
__device__ __forceinline__ void cp16(void* dst, const void* src) {
    uint32_t d = (uint32_t)__cvta_generic_to_shared(dst);
    asm volatile("cp.async.cg.shared.global [%0], [%1], 16;\n" :: "r"(d), "l"(src));
}

// k-permuted fp16 storage: within each 16-k block, pair order
// [0,1,8,9,2,3,10,11,4,5,12,13,6,7,14,15]. psl(k) for even k gives the stored
// index of that pair's first element (odd partner is psl(k)+1).
__device__ __forceinline__ int psl(int k) {
    const int p = (k >> 1) & 7;
    return (k & ~15) | ((((p & 3) << 1) | (p >> 2)) << 1);
}

__device__ __forceinline__ void mma_f16(float4& c, uint32_t a0, uint32_t a1,
                                        uint32_t a2, uint32_t a3,
                                        uint32_t b0, uint32_t b1) {
    asm volatile(
        "mma.sync.aligned.m16n8k16.row.col.f32.f16.f16.f32 "
        "{%0,%1,%2,%3}, {%4,%5,%6,%7}, {%8,%9}, {%0,%1,%2,%3};\n"
        : "+f"(c.x), "+f"(c.y), "+f"(c.z), "+f"(c.w)
        : "r"(a0), "r"(a1), "r"(a2), "r"(a3), "r"(b0), "r"(b1));
}

// ---------------------------------------------------------------------------
// Weight prep: fp32 [N,K] -> k-permuted fp16
// ---------------------------------------------------------------------------
__global__ void __launch_bounds__(256) prep_weights(
    const float* __restrict__ w0, const float* __restrict__ w1,
    const float* __restrict__ w2, const float* __restrict__ w3,
    const float* __restrict__ w4, const float* __restrict__ w5,
    __half* __restrict__ dst)
{
    const size_t i4 = (size_t)blockIdx.x * 256 + threadIdx.x;
    const int seg = (int)(i4 >> 19);            // 524288 float4 per matrix
    const size_t off = (i4 & 524287) * 4;
    const float* src;
    switch (seg) {
        case 0: src = w0; break; case 1: src = w1; break;
        case 2: src = w2; break; case 3: src = w3; break;
        case 4: src = w4; break; default: src = w5; break;
    }
    float4 v = *reinterpret_cast<const float4*>(src + off);
    __half* d = dst + seg * WSEG_H + (off & ~(size_t)15);
    const int j = (int)(off & 15);
    *reinterpret_cast<__half2*>(d + (psl(j) & 15))     = __floats2half2_rn(v.x, v.y);
    *reinterpret_cast<__half2*>(d + (psl(j + 2) & 15)) = __floats2half2_rn(v.z, v.w);
}

// ---------------------------------------------------------------------------
// RMSNorm: fp32 in -> k-permuted fp16 out
// ---------------------------------------------------------------------------
__global__ void __launch_bounds__(256) rmsnorm_kernel(
    const float* __restrict__ x, const float* __restrict__ g,
    __half* __restrict__ out)
{
    const int row = blockIdx.x;
    const int t = threadIdx.x;
    const float4* xr = reinterpret_cast<const float4*>(x) + (size_t)row * (Dc / 4);
    float4 v = xr[t];
    float ss = v.x * v.x + v.y * v.y + v.z * v.z + v.w * v.w;
    #pragma unroll
    for (int off = 16; off > 0; off >>= 1)
        ss += __shfl_down_sync(0xffffffffu, ss, off);
    __shared__ float warp_s[8];
    if ((t & 31) == 0) warp_s[t >> 5] = ss;
    __syncthreads();
    float tot = 0.f;
    #pragma unroll
    for (int i = 0; i < 8; i++) tot += warp_s[i];
    const float scale = rsqrtf(tot * (1.0f / Dc) + 1e-6f);
    float4 gv = reinterpret_cast<const float4*>(g)[t];
    __half* d = out + (size_t)row * Dc;
    const int k = 4 * t;
    *reinterpret_cast<__half2*>(d + psl(k)) =
        __floats2half2_rn(v.x * scale * gv.x, v.y * scale * gv.y);
    *reinterpret_cast<__half2*>(d + psl(k + 2)) =
        __floats2half2_rn(v.z * scale * gv.z, v.w * scale * gv.w);
}

// ---------------------------------------------------------------------------
// fp16 HMMA GEMM: C[M,N] = epilogue(A[M,K] @ W[N,K]^T)
// A, W are k-permuted fp16. BM=128, BN=64, BK=32, 256 threads
// (8 warps: 4m x 2n), warp tile 32x32, m16n8k16 HMMA, fp32 accumulate.
// Smem rows: 32 halfs data, stride 48 halfs (96 B) -> conflict-free LDS.64.
// 3-stage cp.async pipeline.
// MODE 0: dual -> FRI float2 { forget, remember*inp }
// MODE 1: dual -> FF = fp16 permuted( z1 * silu(z2) )
// MODE 2: single -> fp32 z1 + bias + residual
// ---------------------------------------------------------------------------
template <int MODE>
__global__ void __launch_bounds__(256, 2) gemm_f16(
    const __half* __restrict__ A,
    const __half* __restrict__ W1,
    const __half* __restrict__ W2,
    const float* __restrict__ b1,
    const float* __restrict__ b2,
    const float* __restrict__ res,
    float* __restrict__ out,        // MODE1: __half* underneath
    int M, int N, int K)
{
    constexpr bool DUAL = (MODE != 2);
    constexpr int STAGEB = DUAL ? 24576 : 18432;  // bytes per stage
    extern __shared__ char sm[];

    const int tid  = threadIdx.x;
    const int lane = tid & 31;
    const int wid  = tid >> 5;
    const int wm = wid >> 1;           // 0..3
    const int wn = wid & 1;            // 0..1
    const int gid = lane >> 2;         // 0..7
    const int tig = lane & 3;          // 0..3
    const int bm = blockIdx.y * 128;
    const int bn = blockIdx.x * 64;
    const int niter = K >> 5;

    float4 acc1[2][4];
    float4 acc2[2][4];
    #pragma unroll
    for (int i = 0; i < 2; i++)
        #pragma unroll
        for (int j = 0; j < 4; j++) {
            acc1[i][j] = make_float4(0.f, 0.f, 0.f, 0.f);
            acc2[i][j] = make_float4(0.f, 0.f, 0.f, 0.f);
        }

    auto load_stage = [&](int slot, int it) {
        char* st = sm + slot * STAGEB;
        const int k0 = it << 5;
        // A: 128 rows x 64 B -> 512 x 16 B chunks
        #pragma unroll
        for (int i = 0; i < 2; i++) {
            int q = tid + (i << 8);
            int r = q >> 2, c = q & 3;
            cp16(st + r * 96 + c * 16, A + (size_t)(bm + r) * K + k0 + c * 8);
        }
        // B1 (and B2): 64 rows x 64 B -> 256 chunks each
        {
            int r = tid >> 2, c = tid & 3;
            cp16(st + 12288 + r * 96 + c * 16,
                 W1 + (size_t)(bn + r) * K + k0 + c * 8);
            if (DUAL)
                cp16(st + 18432 + r * 96 + c * 16,
                     W2 + (size_t)(bn + r) * K + k0 + c * 8);
        }
    };

    load_stage(0, 0);
    asm volatile("cp.async.commit_group;\n");
    load_stage(1, 1);
    asm volatile("cp.async.commit_group;\n");

    int slot = 0;
    for (int it = 0; it < niter; ++it) {
        if (it + 2 < niter)
            load_stage((it + 2) % 3, it + 2);
        asm volatile("cp.async.commit_group;\n");
        asm volatile("cp.async.wait_group 2;\n");
        __syncthreads();

        const char* st = sm + slot * STAGEB;
        const __half* As = reinterpret_cast<const __half*>(st);
        const __half* B1s = reinterpret_cast<const __half*>(st + 12288);
        const __half* B2s = reinterpret_cast<const __half*>(st + 18432);

        #pragma unroll
        for (int ks = 0; ks < 2; ks++) {
            const int ko = ks * 16 + 4 * tig;
            uint2 alo[2], ahi[2];
            #pragma unroll
            for (int mf = 0; mf < 2; mf++) {
                const int r = wm * 32 + mf * 16 + gid;
                alo[mf] = *reinterpret_cast<const uint2*>(As + r * 48 + ko);
                ahi[mf] = *reinterpret_cast<const uint2*>(As + (r + 8) * 48 + ko);
            }
            #pragma unroll
            for (int nf = 0; nf < 4; nf++) {
                const int n = wn * 32 + nf * 8 + gid;
                const uint2 bv = *reinterpret_cast<const uint2*>(B1s + n * 48 + ko);
                uint2 cv;
                if (DUAL) cv = *reinterpret_cast<const uint2*>(B2s + n * 48 + ko);
                #pragma unroll
                for (int mf = 0; mf < 2; mf++) {
                    mma_f16(acc1[mf][nf], alo[mf].x, ahi[mf].x, alo[mf].y, ahi[mf].y,
                            bv.x, bv.y);
                    if (DUAL)
                        mma_f16(acc2[mf][nf], alo[mf].x, ahi[mf].x, alo[mf].y, ahi[mf].y,
                                cv.x, cv.y);
                }
            }
        }
        __syncthreads();
        slot = (slot + 1 == 3) ? 0 : slot + 1;
    }

    // ------------------------------ Epilogue ------------------------------
    #pragma unroll
    for (int nf = 0; nf < 4; nf++) {
        const int c0 = bn + wn * 32 + nf * 8 + 2 * tig;   // even
        const float bias1a = b1[c0], bias1b = b1[c0 + 1];
        float bias2a = 0.f, bias2b = 0.f;
        if (DUAL) { bias2a = b2[c0]; bias2b = b2[c0 + 1]; }
        float decaya = 0.f, decayb = 0.f;
        if (MODE == 0) {
            const float inv = 1.0f / (float)(N - 1);
            decaya = (float)c0 * inv;
            decayb = (float)(c0 + 1) * inv;
        }
        #pragma unroll
        for (int mf = 0; mf < 2; mf++) {
            const float4 a1 = acc1[mf][nf];
            const float4 a2 = acc2[mf][nf];
            #pragma unroll
            for (int h = 0; h < 2; h++) {
                const int r = bm + wm * 32 + mf * 16 + gid + h * 8;
                const float z1a = (h ? a1.z : a1.x) + bias1a;
                const float z1b = (h ? a1.w : a1.y) + bias1b;
                if (MODE == 0) {
                    const float z2a = (h ? a2.z : a2.x) + bias2a;
                    const float z2b = (h ? a2.w : a2.y) + bias2b;
                    const float rema = decaya * sigmoidf_(z1a);
                    const float remb = decayb * sigmoidf_(z1b);
                    float4 o;
                    o.x = 1.0f - rema;  o.y = rema * tanhf(z2a);
                    o.z = 1.0f - remb;  o.w = remb * tanhf(z2b);
                    *reinterpret_cast<float4*>(
                        reinterpret_cast<float2*>(out) + (size_t)r * N + c0) = o;
                } else if (MODE == 1) {
                    const float z2a = (h ? a2.z : a2.x) + bias2a;
                    const float z2b = (h ? a2.w : a2.y) + bias2b;
                    const float fa = z1a * (z2a * sigmoidf_(z2a));
                    const float fb = z1b * (z2b * sigmoidf_(z2b));
                    __half* fo = reinterpret_cast<__half*>(out) + (size_t)r * N;
                    *reinterpret_cast<__half2*>(fo + psl(c0)) = __floats2half2_rn(fa, fb);
                } else {
                    const size_t idx = (size_t)r * N + c0;
                    const float2 rv = *reinterpret_cast<const float2*>(res + idx);
                    float2 o;
                    o.x = z1a + rv.x;
                    o.y = z1b + rv.y;
                    *reinterpret_cast<float2*>(out + idx) = o;
                }
            }
        }
    }
    (void)M;
}

// ---------------------------------------------------------------------------
// Chunked scan: 64 chunks x 64 steps per (b,h) channel.
// ---------------------------------------------------------------------------
__global__ void __launch_bounds__(256) scan_chunk(
    const float2* __restrict__ fri, float2* __restrict__ ab)
{
    const int idx = blockIdx.x * 256 + threadIdx.x;   // B*64*H
    const int h = idx & (Hc - 1);
    const int rest = idx >> 11;
    const int c = rest & 63;
    const int b = rest >> 6;
    const float2* p = fri + ((size_t)b * Lc + (size_t)c * 64) * Hc + h;
    float a = 1.0f, s = 0.0f;
    for (int t = 0; t < 64; t += 8) {
        float2 v[8];
        #pragma unroll
        for (int u = 0; u < 8; u++) v[u] = p[(size_t)(t + u) * Hc];
        #pragma unroll
        for (int u = 0; u < 8; u++) {
            s = fmaf(v[u].x, s, v[u].y);
            a *= v[u].x;
        }
    }
    ab[idx] = make_float2(a, s);
}

__global__ void __launch_bounds__(256) scan_carry(
    const float2* __restrict__ ab, const float* __restrict__ hidden,
    float* __restrict__ cin, float* __restrict__ hlast)
{
    const int idx = blockIdx.x * 256 + threadIdx.x;   // B*H
    const int h = idx & (Hc - 1);
    const int b = idx >> 11;
    float carry = hidden[idx];
    for (int c = 0; c < 64; c++) {
        const size_t o = ((size_t)(b * 64 + c) << 11) + h;
        cin[o] = carry;
        const float2 v = ab[o];
        carry = fmaf(v.x, carry, v.y);
    }
    hlast[idx] = carry;
}

// Re-apply with correct carry-in; HBUF written as k-permuted fp16.
__global__ void __launch_bounds__(256) scan_apply(
    const float2* __restrict__ fri, const float* __restrict__ cin,
    __half* __restrict__ hbuf)
{
    const int idx = blockIdx.x * 256 + threadIdx.x;   // B*64*H
    const int h = idx & (Hc - 1);
    const int rest = idx >> 11;
    const int c = rest & 63;
    const int b = rest >> 6;
    const size_t off = ((size_t)b * Lc + (size_t)c * 64) * Hc;
    const float2* p = fri + off + h;
    const int scol = psl(h & ~1) + (h & 1);
    __half* o = hbuf + off + scol;
    float carry = cin[idx];
    for (int t = 0; t < 64; t += 8) {
        float2 v[8];
        #pragma unroll
        for (int u = 0; u < 8; u++) v[u] = p[(size_t)(t + u) * Hc];
        #pragma unroll
        for (int u = 0; u < 8; u++) {
            carry = fmaf(v[u].x, carry, v[u].y);
            o[(size_t)(t + u) * Hc] = __float2half_rn(carry);
        }
    }
}

// ---------------------------------------------------------------------------
// kernel_launch
// ---------------------------------------------------------------------------
extern "C" void kernel_launch(void* const* d_in, const int* in_sizes, int n_in,
                              void* d_out, int out_size)
{
    const float* x        = (const float*)d_in[0];
    const float* hidden   = (const float*)d_in[1];
    const float* w_forget = (const float*)d_in[2];
    const float* b_forget = (const float*)d_in[3];
    const float* w_input  = (const float*)d_in[4];
    const float* b_input  = (const float*)d_in[5];
    const float* w_hout   = (const float*)d_in[6];
    const float* b_hout   = (const float*)d_in[7];
    const float* w_fc     = (const float*)d_in[8];
    const float* b_fc     = (const float*)d_in[9];
    const float* w_fc_act = (const float*)d_in[10];
    const float* b_fc_act = (const float*)d_in[11];
    const float* w_fout   = (const float*)d_in[12];
    const float* b_fout   = (const float*)d_in[13];
    const float* g_norm1  = (const float*)d_in[14];
    const float* g_norm2  = (const float*)d_in[15];
    float* out = (float*)d_out;

    float* gbuf = nullptr;
    cudaGetSymbolAddress((void**)&gbuf, g_buf);
    float*  FRI  = gbuf + OFF_FRI;
    __half* HBUF = (__half*)(gbuf + OFF_HBUF);
    float*  X1   = gbuf + OFF_X1;
    __half* XN   = (__half*)(gbuf + OFF_XN);
    __half* XN2  = (__half*)(gbuf + OFF_XN2);
    __half* FF   = (__half*)(gbuf + OFF_FF);
    __half* WT   = (__half*)(gbuf + OFF_WT);
    float*  AB   = gbuf + OFF_AB;
    float*  CIN  = gbuf + OFF_CIN;

    const int smem_dual   = 3 * 24576;  // 73728
    const int smem_single = 3 * 18432;  // 55296
    static bool attr_done = false;
    if (!attr_done) {
        cudaFuncSetAttribute(gemm_f16<0>, cudaFuncAttributeMaxDynamicSharedMemorySize, smem_dual);
        cudaFuncSetAttribute(gemm_f16<1>, cudaFuncAttributeMaxDynamicSharedMemorySize, smem_dual);
        cudaFuncSetAttribute(gemm_f16<2>, cudaFuncAttributeMaxDynamicSharedMemorySize, smem_single);
        attr_done = true;
    }

    // 0. fp16-permute all weights into scratch
    prep_weights<<<12288, 256>>>(w_forget, w_input, w_hout, w_fc, w_fc_act, w_fout, WT);
    const __half* Wf   = WT + 0 * WSEG_H;
    const __half* Wi   = WT + 1 * WSEG_H;
    const __half* Who  = WT + 2 * WSEG_H;
    const __half* Wfc  = WT + 3 * WSEG_H;
    const __half* Wfca = WT + 4 * WSEG_H;
    const __half* Wfo  = WT + 5 * WSEG_H;

    // 1. xn = fp16(rmsnorm(x) * g1), k-permuted
    rmsnorm_kernel<<<Mrows, 256>>>(x, g_norm1, XN);

    // 2. dual GEMM -> (forget, remember*inp) fp32 float2
    gemm_f16<0><<<dim3(Hc / 64, Mrows / 128), 256, smem_dual>>>(
        XN, Wf, Wi, b_forget, b_input, nullptr, FRI, Mrows, Hc, Dc);

    // 3. chunked recurrence scan (h_last -> output tail)
    scan_chunk<<<(Bc * 64 * Hc) / 256, 256>>>((const float2*)FRI, (float2*)AB);
    scan_carry<<<(Bc * Hc) / 256, 256>>>((const float2*)AB, hidden, CIN, out + BLD);
    scan_apply<<<(Bc * 64 * Hc) / 256, 256>>>((const float2*)FRI, CIN, HBUF);

    // 4. x1 = h @ w_hout^T + b_hout + x      (fp32 out)
    gemm_f16<2><<<dim3(Dc / 64, Mrows / 128), 256, smem_single>>>(
        HBUF, Who, nullptr, b_hout, nullptr, x, X1, Mrows, Dc, Hc);

    // 5. xn2 = fp16(rmsnorm(x1) * g2), k-permuted
    rmsnorm_kernel<<<Mrows, 256>>>(X1, g_norm2, XN2);

    // 6. dual GEMM -> ff = fc * silu(fc_act)  (fp16 permuted out)
    gemm_f16<1><<<dim3(Hc / 64, Mrows / 128), 256, smem_dual>>>(
        XN2, Wfc, Wfca, b_fc, b_fc_act, nullptr, (float*)FF, Mrows, Hc, Dc);

    // 7. out = ff @ w_fout^T + b_fout + x1   (fp32 out)
    gemm_f16<2><<<dim3(Dc / 64, Mrows / 128), 256, smem_single>>>(
        FF, Wfo, nullptr, b_fout, nullptr, X1, out, Mrows, Dc, Hc);

    (void)in_sizes; (void)n_in; (void)out_size;
}

// round 8
// speedup vs baseline: 6.2425x; 1.0105x over previous
#include <cuda_runtime.h>
#include <cuda_fp16.h>
#include <math.h>
#include <stdint.h>

// Problem shape (fixed by setup_inputs)
#define Bc 4
#define Lc 4096
#define Dc 1024
#define Hc 2048
#define Mrows (Bc * Lc)            // 16384
#define BLD ((size_t)Mrows * Dc)   // 16,777,216

// ---------------------------------------------------------------------------
// Scratch regions (float units)
//   FFp  fp32 [16384,2048] forget        @ 0          (33,554,432 floats)
//   RIp  fp16 [16384,2048] rem*inp       @ 33554432   (16,777,216 floats)
//   HBUF half [16384,2048] permuted      @ 50331648   (16,777,216 floats)
//   X1   fp32 [16384,1024]               @ 67108864   (16,777,216 floats)
//   XN   half [16384,1024] permuted      @ 83886080   ( 8,388,608 floats)
//   XN2  half [16384,1024] permuted      @ 92274688   ( 8,388,608 floats)
//   FF   half [16384,2048] permuted      @ 100663296  (16,777,216 floats)
//   WT   half 6 x 2,097,152 permuted     @ 117440512  ( 6,291,456 floats)
//   AB   float2 [4*64*2048]              @ 123731968  ( 1,048,576 floats)
//   CIN  float  [4*64*2048]              @ 124780544  (   524,288 floats)
// total 125,304,832 floats = 501 MB
// ---------------------------------------------------------------------------
__device__ float g_buf[125304832];

#define OFF_FFP  ((size_t)0)
#define OFF_RIP  ((size_t)33554432)
#define OFF_HBUF ((size_t)50331648)
#define OFF_X1   ((size_t)67108864)
#define OFF_XN   ((size_t)83886080)
#define OFF_XN2  ((size_t)92274688)
#define OFF_FF   ((size_t)100663296)
#define OFF_WT   ((size_t)117440512)
#define OFF_AB   ((size_t)123731968)
#define OFF_CIN  ((size_t)124780544)

#define WSEG_H ((size_t)2097152)   // halfs per weight matrix

// ---------------------------------------------------------------------------
// helpers
// ---------------------------------------------------------------------------
__device__ __forceinline__ float sigmoidf_(float x) {
    return 1.0f / (1.0f + expf(-x));
}
__device__ __forceinline__ void cp16(void* dst, const void* src) {
    uint32_t d = (uint32_t)__cvta_generic_to_shared(dst);
    asm volatile("cp.async.cg.shared.global [%0], [%1], 16;\n" :: "r"(d), "l"(src));
}

// k-permuted fp16 storage: within each 16-k block, pair order
// [0,1,8,9,2,3,10,11,4,5,12,13,6,7,14,15]. psl(k) for even k gives the stored
// index of that pair's first element (odd partner is psl(k)+1).
__device__ __forceinline__ int psl(int k) {
    const int p = (k >> 1) & 7;
    return (k & ~15) | ((((p & 3) << 1) | (p >> 2)) << 1);
}

__device__ __forceinline__ void mma_f16(float4& c, uint32_t a0, uint32_t a1,
                                        uint32_t a2, uint32_t a3,
                                        uint32_t b0, uint32_t b1) {
    asm volatile(
        "mma.sync.aligned.m16n8k16.row.col.f32.f16.f16.f32 "
        "{%0,%1,%2,%3}, {%4,%5,%6,%7}, {%8,%9}, {%0,%1,%2,%3};\n"
        : "+f"(c.x), "+f"(c.y), "+f"(c.z), "+f"(c.w)
        : "r"(a0), "r"(a1), "r"(a2), "r"(a3), "r"(b0), "r"(b1));
}

// ---------------------------------------------------------------------------
// Weight prep: fp32 [N,K] -> k-permuted fp16
// ---------------------------------------------------------------------------
__global__ void __launch_bounds__(256) prep_weights(
    const float* __restrict__ w0, const float* __restrict__ w1,
    const float* __restrict__ w2, const float* __restrict__ w3,
    const float* __restrict__ w4, const float* __restrict__ w5,
    __half* __restrict__ dst)
{
    const size_t i4 = (size_t)blockIdx.x * 256 + threadIdx.x;
    const int seg = (int)(i4 >> 19);            // 524288 float4 per matrix
    const size_t off = (i4 & 524287) * 4;
    const float* src;
    switch (seg) {
        case 0: src = w0; break; case 1: src = w1; break;
        case 2: src = w2; break; case 3: src = w3; break;
        case 4: src = w4; break; default: src = w5; break;
    }
    float4 v = *reinterpret_cast<const float4*>(src + off);
    __half* d = dst + seg * WSEG_H + (off & ~(size_t)15);
    const int j = (int)(off & 15);
    *reinterpret_cast<__half2*>(d + (psl(j) & 15))     = __floats2half2_rn(v.x, v.y);
    *reinterpret_cast<__half2*>(d + (psl(j + 2) & 15)) = __floats2half2_rn(v.z, v.w);
}

// ---------------------------------------------------------------------------
// RMSNorm: fp32 in -> k-permuted fp16 out
// ---------------------------------------------------------------------------
__global__ void __launch_bounds__(256) rmsnorm_kernel(
    const float* __restrict__ x, const float* __restrict__ g,
    __half* __restrict__ out)
{
    const int row = blockIdx.x;
    const int t = threadIdx.x;
    const float4* xr = reinterpret_cast<const float4*>(x) + (size_t)row * (Dc / 4);
    float4 v = xr[t];
    float ss = v.x * v.x + v.y * v.y + v.z * v.z + v.w * v.w;
    #pragma unroll
    for (int off = 16; off > 0; off >>= 1)
        ss += __shfl_down_sync(0xffffffffu, ss, off);
    __shared__ float warp_s[8];
    if ((t & 31) == 0) warp_s[t >> 5] = ss;
    __syncthreads();
    float tot = 0.f;
    #pragma unroll
    for (int i = 0; i < 8; i++) tot += warp_s[i];
    const float scale = rsqrtf(tot * (1.0f / Dc) + 1e-6f);
    float4 gv = reinterpret_cast<const float4*>(g)[t];
    __half* d = out + (size_t)row * Dc;
    const int k = 4 * t;
    *reinterpret_cast<__half2*>(d + psl(k)) =
        __floats2half2_rn(v.x * scale * gv.x, v.y * scale * gv.y);
    *reinterpret_cast<__half2*>(d + psl(k + 2)) =
        __floats2half2_rn(v.z * scale * gv.z, v.w * scale * gv.w);
}

// ---------------------------------------------------------------------------
// fp16 HMMA GEMM: C[M,N] = epilogue(A[M,K] @ W[N,K]^T)
// A, W are k-permuted fp16. BM=128, BN=64, BK=32, 256 threads
// (8 warps: 4m x 2n), warp tile 32x32, m16n8k16 HMMA, fp32 accumulate.
// Smem rows: 32 halfs data, stride 48 halfs (96 B) -> conflict-free LDS.64.
// 3-stage cp.async pipeline.
// MODE 0: dual -> SoA forget fp32 / rem*inp fp16, PLUS fused per-chunk (A,S)
//         scan aggregates written to AB (tile = 2 chunks x 64 cols).
// MODE 1: dual -> FF = fp16 permuted( z1 * silu(z2) )
// MODE 2: single -> fp32 z1 + bias + residual
// ---------------------------------------------------------------------------
template <int MODE>
__global__ void __launch_bounds__(256, 2) gemm_f16(
    const __half* __restrict__ A,
    const __half* __restrict__ W1,
    const __half* __restrict__ W2,
    const float* __restrict__ b1,
    const float* __restrict__ b2,
    const float* __restrict__ res,
    float* __restrict__ out,         // MODE0: forget plane; MODE1: __half* FF
    __half* __restrict__ out_h,      // MODE0: ri plane
    float2* __restrict__ ab,         // MODE0: chunk aggregates
    int M, int N, int K)
{
    constexpr bool DUAL = (MODE != 2);
    constexpr int STAGEB = DUAL ? 24576 : 18432;  // bytes per stage
    extern __shared__ char sm[];

    const int tid  = threadIdx.x;
    const int lane = tid & 31;
    const int wid  = tid >> 5;
    const int wm = wid >> 1;           // 0..3
    const int wn = wid & 1;            // 0..1
    const int gid = lane >> 2;         // 0..7
    const int tig = lane & 3;          // 0..3
    const int bm = blockIdx.y * 128;
    const int bn = blockIdx.x * 64;
    const int niter = K >> 5;

    float4 acc1[2][4];
    float4 acc2[2][4];
    #pragma unroll
    for (int i = 0; i < 2; i++)
        #pragma unroll
        for (int j = 0; j < 4; j++) {
            acc1[i][j] = make_float4(0.f, 0.f, 0.f, 0.f);
            acc2[i][j] = make_float4(0.f, 0.f, 0.f, 0.f);
        }

    auto load_stage = [&](int slot, int it) {
        char* st = sm + slot * STAGEB;
        const int k0 = it << 5;
        #pragma unroll
        for (int i = 0; i < 2; i++) {
            int q = tid + (i << 8);
            int r = q >> 2, c = q & 3;
            cp16(st + r * 96 + c * 16, A + (size_t)(bm + r) * K + k0 + c * 8);
        }
        {
            int r = tid >> 2, c = tid & 3;
            cp16(st + 12288 + r * 96 + c * 16,
                 W1 + (size_t)(bn + r) * K + k0 + c * 8);
            if (DUAL)
                cp16(st + 18432 + r * 96 + c * 16,
                     W2 + (size_t)(bn + r) * K + k0 + c * 8);
        }
    };

    load_stage(0, 0);
    asm volatile("cp.async.commit_group;\n");
    load_stage(1, 1);
    asm volatile("cp.async.commit_group;\n");

    int slot = 0;
    for (int it = 0; it < niter; ++it) {
        if (it + 2 < niter)
            load_stage((it + 2) % 3, it + 2);
        asm volatile("cp.async.commit_group;\n");
        asm volatile("cp.async.wait_group 2;\n");
        __syncthreads();

        const char* st = sm + slot * STAGEB;
        const __half* As = reinterpret_cast<const __half*>(st);
        const __half* B1s = reinterpret_cast<const __half*>(st + 12288);
        const __half* B2s = reinterpret_cast<const __half*>(st + 18432);

        #pragma unroll
        for (int ks = 0; ks < 2; ks++) {
            const int ko = ks * 16 + 4 * tig;
            uint2 alo[2], ahi[2];
            #pragma unroll
            for (int mf = 0; mf < 2; mf++) {
                const int r = wm * 32 + mf * 16 + gid;
                alo[mf] = *reinterpret_cast<const uint2*>(As + r * 48 + ko);
                ahi[mf] = *reinterpret_cast<const uint2*>(As + (r + 8) * 48 + ko);
            }
            #pragma unroll
            for (int nf = 0; nf < 4; nf++) {
                const int n = wn * 32 + nf * 8 + gid;
                const uint2 bv = *reinterpret_cast<const uint2*>(B1s + n * 48 + ko);
                uint2 cv;
                if (DUAL) cv = *reinterpret_cast<const uint2*>(B2s + n * 48 + ko);
                #pragma unroll
                for (int mf = 0; mf < 2; mf++) {
                    mma_f16(acc1[mf][nf], alo[mf].x, ahi[mf].x, alo[mf].y, ahi[mf].y,
                            bv.x, bv.y);
                    if (DUAL)
                        mma_f16(acc2[mf][nf], alo[mf].x, ahi[mf].x, alo[mf].y, ahi[mf].y,
                                cv.x, cv.y);
                }
            }
        }
        __syncthreads();
        slot = (slot + 1 == 3) ? 0 : slot + 1;
    }

    // ------------------------------ Epilogue ------------------------------
    // MODE0 staging buffer for the fused chunk-scan: float2 (f, ri) per cell,
    // row stride 65 float2 -> 128*65*8 = 66560 B <= 73728 B pipeline smem.
    float2* stg = reinterpret_cast<float2*>(sm);

    #pragma unroll
    for (int nf = 0; nf < 4; nf++) {
        const int cl0 = wn * 32 + nf * 8 + 2 * tig;       // local col (even)
        const int c0 = bn + cl0;
        const float bias1a = b1[c0], bias1b = b1[c0 + 1];
        float bias2a = 0.f, bias2b = 0.f;
        if (DUAL) { bias2a = b2[c0]; bias2b = b2[c0 + 1]; }
        float decaya = 0.f, decayb = 0.f;
        if (MODE == 0) {
            const float inv = 1.0f / (float)(N - 1);
            decaya = (float)c0 * inv;
            decayb = (float)(c0 + 1) * inv;
        }
        #pragma unroll
        for (int mf = 0; mf < 2; mf++) {
            const float4 a1 = acc1[mf][nf];
            const float4 a2 = acc2[mf][nf];
            #pragma unroll
            for (int h = 0; h < 2; h++) {
                const int rl = wm * 32 + mf * 16 + gid + h * 8;   // local row
                const int r = bm + rl;
                const float z1a = (h ? a1.z : a1.x) + bias1a;
                const float z1b = (h ? a1.w : a1.y) + bias1b;
                if (MODE == 0) {
                    const float z2a = (h ? a2.z : a2.x) + bias2a;
                    const float z2b = (h ? a2.w : a2.y) + bias2b;
                    const float rema = decaya * sigmoidf_(z1a);
                    const float remb = decayb * sigmoidf_(z1b);
                    const float fa = 1.0f - rema;
                    const float fb = 1.0f - remb;
                    const float ria = rema * tanhf(z2a);
                    const float rib = remb * tanhf(z2b);
                    const size_t idx = (size_t)r * N + c0;
                    *reinterpret_cast<float2*>(out + idx) = make_float2(fa, fb);
                    *reinterpret_cast<__half2*>(out_h + idx) = __floats2half2_rn(ria, rib);
                    stg[rl * 65 + cl0]     = make_float2(fa, ria);
                    stg[rl * 65 + cl0 + 1] = make_float2(fb, rib);
                } else if (MODE == 1) {
                    const float z2a = (h ? a2.z : a2.x) + bias2a;
                    const float z2b = (h ? a2.w : a2.y) + bias2b;
                    const float va = z1a * (z2a * sigmoidf_(z2a));
                    const float vb = z1b * (z2b * sigmoidf_(z2b));
                    __half* fo = reinterpret_cast<__half*>(out) + (size_t)r * N;
                    *reinterpret_cast<__half2*>(fo + psl(c0)) = __floats2half2_rn(va, vb);
                } else {
                    const size_t idx = (size_t)r * N + c0;
                    const float2 rv = *reinterpret_cast<const float2*>(res + idx);
                    float2 o;
                    o.x = z1a + rv.x;
                    o.y = z1b + rv.y;
                    *reinterpret_cast<float2*>(out + idx) = o;
                }
            }
        }
    }

    if (MODE == 0) {
        // Fused chunk-scan: 128 chains (2 chunks x 64 cols), 64 steps each.
        __syncthreads();
        if (tid < 128) {
            const int chunk = tid >> 6;      // 0..1
            const int col = tid & 63;        // 0..63
            const float2* p = stg + (chunk * 64) * 65 + col;
            float a = 1.0f, s = 0.0f;
            #pragma unroll 8
            for (int rr = 0; rr < 64; rr++) {
                const float2 v = p[rr * 65];
                s = fmaf(v.x, s, v.y);
                a *= v.x;
            }
            const int b = bm >> 12;                       // bm / 4096
            const int cglob = ((bm & 4095) >> 6) + chunk; // chunk index in b
            ab[((size_t)(b * 64 + cglob) << 11) + bn + col] = make_float2(a, s);
        }
    }
    (void)M;
}

// ---------------------------------------------------------------------------
// Cross-chunk carry: serial over 64 chunks, channel pairs.
// ---------------------------------------------------------------------------
__global__ void __launch_bounds__(256) scan_carry(
    const float4* __restrict__ ab4,     // (a0,s0,a1,s1) per channel pair
    const float2* __restrict__ hidden2,
    float2* __restrict__ cin2,
    float2* __restrict__ hlast2)
{
    const int idx = blockIdx.x * 256 + threadIdx.x;   // 0 .. B*H/2-1
    const int b = idx >> 10;
    const int hp = idx & 1023;
    float2 carry = hidden2[idx];
    for (int c = 0; c < 64; c++) {
        const size_t o = ((size_t)(b * 64 + c) << 10) + hp;
        cin2[o] = carry;
        const float4 v = ab4[o];
        carry.x = fmaf(v.x, carry.x, v.y);
        carry.y = fmaf(v.z, carry.y, v.w);
    }
    hlast2[idx] = carry;
}

// ---------------------------------------------------------------------------
// Re-apply with correct carry-in; channel pairs; HBUF written k-permuted fp16.
// ---------------------------------------------------------------------------
__global__ void __launch_bounds__(256) scan_apply(
    const float2* __restrict__ ffp2,    // forget pairs
    const __half2* __restrict__ rip2,   // ri pairs
    const float2* __restrict__ cin2,
    __half2* __restrict__ hbuf2)
{
    const int idx = blockIdx.x * 256 + threadIdx.x;   // B*64*1024 pairs
    const int hp = idx & 1023;
    const int rest = idx >> 10;
    const int c = rest & 63;
    const int b = rest >> 6;
    const size_t offp = ((size_t)b * Lc + (size_t)c * 64) * (Hc / 2);  // in pairs
    const float2* pf = ffp2 + offp + hp;
    const __half2* pr = rip2 + offp + hp;
    __half2* o = hbuf2 + offp + (psl(2 * hp) >> 1);
    float2 carry = cin2[idx];
    for (int t = 0; t < 64; t += 8) {
        float2 f[8]; __half2 r[8];
        #pragma unroll
        for (int u = 0; u < 8; u++) {
            f[u] = pf[(size_t)(t + u) * (Hc / 2)];
            r[u] = pr[(size_t)(t + u) * (Hc / 2)];
        }
        #pragma unroll
        for (int u = 0; u < 8; u++) {
            const float2 rv = __half22float2(r[u]);
            carry.x = fmaf(f[u].x, carry.x, rv.x);
            carry.y = fmaf(f[u].y, carry.y, rv.y);
            o[(size_t)(t + u) * (Hc / 2)] = __floats2half2_rn(carry.x, carry.y);
        }
    }
}

// ---------------------------------------------------------------------------
// kernel_launch
// ---------------------------------------------------------------------------
extern "C" void kernel_launch(void* const* d_in, const int* in_sizes, int n_in,
                              void* d_out, int out_size)
{
    const float* x        = (const float*)d_in[0];
    const float* hidden   = (const float*)d_in[1];
    const float* w_forget = (const float*)d_in[2];
    const float* b_forget = (const float*)d_in[3];
    const float* w_input  = (const float*)d_in[4];
    const float* b_input  = (const float*)d_in[5];
    const float* w_hout   = (const float*)d_in[6];
    const float* b_hout   = (const float*)d_in[7];
    const float* w_fc     = (const float*)d_in[8];
    const float* b_fc     = (const float*)d_in[9];
    const float* w_fc_act = (const float*)d_in[10];
    const float* b_fc_act = (const float*)d_in[11];
    const float* w_fout   = (const float*)d_in[12];
    const float* b_fout   = (const float*)d_in[13];
    const float* g_norm1  = (const float*)d_in[14];
    const float* g_norm2  = (const float*)d_in[15];
    float* out = (float*)d_out;

    float* gbuf = nullptr;
    cudaGetSymbolAddress((void**)&gbuf, g_buf);
    float*  FFp  = gbuf + OFF_FFP;
    __half* RIp  = (__half*)(gbuf + OFF_RIP);
    __half* HBUF = (__half*)(gbuf + OFF_HBUF);
    float*  X1   = gbuf + OFF_X1;
    __half* XN   = (__half*)(gbuf + OFF_XN);
    __half* XN2  = (__half*)(gbuf + OFF_XN2);
    __half* FF   = (__half*)(gbuf + OFF_FF);
    __half* WT   = (__half*)(gbuf + OFF_WT);
    float*  AB   = gbuf + OFF_AB;
    float*  CIN  = gbuf + OFF_CIN;

    const int smem_dual   = 3 * 24576;  // 73728
    const int smem_single = 3 * 18432;  // 55296
    static bool attr_done = false;
    if (!attr_done) {
        cudaFuncSetAttribute(gemm_f16<0>, cudaFuncAttributeMaxDynamicSharedMemorySize, smem_dual);
        cudaFuncSetAttribute(gemm_f16<1>, cudaFuncAttributeMaxDynamicSharedMemorySize, smem_dual);
        cudaFuncSetAttribute(gemm_f16<2>, cudaFuncAttributeMaxDynamicSharedMemorySize, smem_single);
        attr_done = true;
    }

    // 0. fp16-permute all weights into scratch
    prep_weights<<<12288, 256>>>(w_forget, w_input, w_hout, w_fc, w_fc_act, w_fout, WT);
    const __half* Wf   = WT + 0 * WSEG_H;
    const __half* Wi   = WT + 1 * WSEG_H;
    const __half* Who  = WT + 2 * WSEG_H;
    const __half* Wfc  = WT + 3 * WSEG_H;
    const __half* Wfca = WT + 4 * WSEG_H;
    const __half* Wfo  = WT + 5 * WSEG_H;

    // 1. xn = fp16(rmsnorm(x) * g1), k-permuted
    rmsnorm_kernel<<<Mrows, 256>>>(x, g_norm1, XN);

    // 2. dual GEMM -> SoA (forget fp32, ri fp16) + fused chunk aggregates
    gemm_f16<0><<<dim3(Hc / 64, Mrows / 128), 256, smem_dual>>>(
        XN, Wf, Wi, b_forget, b_input, nullptr, FFp, RIp, (float2*)AB,
        Mrows, Hc, Dc);

    // 3. carry across chunks (h_last -> output tail), then re-apply
    scan_carry<<<(Bc * Hc / 2) / 256, 256>>>(
        (const float4*)AB, (const float2*)hidden, (float2*)CIN,
        (float2*)(out + BLD));
    scan_apply<<<(Bc * 64 * Hc / 2) / 256, 256>>>(
        (const float2*)FFp, (const __half2*)RIp, (const float2*)CIN,
        (__half2*)HBUF);

    // 4. x1 = h @ w_hout^T + b_hout + x      (fp32 out)
    gemm_f16<2><<<dim3(Dc / 64, Mrows / 128), 256, smem_single>>>(
        HBUF, Who, nullptr, b_hout, nullptr, x, X1, nullptr, nullptr,
        Mrows, Dc, Hc);

    // 5. xn2 = fp16(rmsnorm(x1) * g2), k-permuted
    rmsnorm_kernel<<<Mrows, 256>>>(X1, g_norm2, XN2);

    // 6. dual GEMM -> ff = fc * silu(fc_act)  (fp16 permuted out)
    gemm_f16<1><<<dim3(Hc / 64, Mrows / 128), 256, smem_dual>>>(
        XN2, Wfc, Wfca, b_fc, b_fc_act, nullptr, (float*)FF, nullptr, nullptr,
        Mrows, Hc, Dc);

    // 7. out = ff @ w_fout^T + b_fout + x1   (fp32 out)
    gemm_f16<2><<<dim3(Dc / 64, Mrows / 128), 256, smem_single>>>(
        FF, Wfo, nullptr, b_fout, nullptr, X1, out, nullptr, nullptr,
        Mrows, Dc, Hc);

    (void)in_sizes; (void)n_in; (void)out_size;
}

// round 9
// speedup vs baseline: 6.2964x; 1.0086x over previous
#include <cuda_runtime.h>
#include <cuda_fp16.h>
#include <math.h>
#include <stdint.h>

// Problem shape (fixed by setup_inputs)
#define Bc 4
#define Lc 4096
#define Dc 1024
#define Hc 2048
#define Mrows (Bc * Lc)            // 16384
#define BLD ((size_t)Mrows * Dc)   // 16,777,216

// ---------------------------------------------------------------------------
// Scratch regions (float units)
//   REMp fp16 [16384,2048] remember      @ 0          (16,777,216 floats)
//   RIp  fp16 [16384,2048] rem*inp       @ 16777216   (16,777,216 floats)
//   HBUF half [16384,2048] permuted      @ 33554432   (16,777,216 floats)
//   X1   fp32 [16384,1024]               @ 50331648   (16,777,216 floats)
//   XN   half [16384,1024] permuted      @ 67108864   ( 8,388,608 floats)
//   XN2  half [16384,1024] permuted      @ 75497472   ( 8,388,608 floats)
//   FF   half [16384,2048] permuted      @ 83886080   (16,777,216 floats)
//   WT   half 6 x 2,097,152 permuted     @ 100663296  ( 6,291,456 floats)
//   AB   float2 [4*64*2048]              @ 106954752  ( 1,048,576 floats)
//   CIN  float  [4*64*2048]              @ 108003328  (   524,288 floats)
// total 108,527,616 floats = 434 MB
// ---------------------------------------------------------------------------
__device__ float g_buf[108527616];

#define OFF_REMP ((size_t)0)
#define OFF_RIP  ((size_t)16777216)
#define OFF_HBUF ((size_t)33554432)
#define OFF_X1   ((size_t)50331648)
#define OFF_XN   ((size_t)67108864)
#define OFF_XN2  ((size_t)75497472)
#define OFF_FF   ((size_t)83886080)
#define OFF_WT   ((size_t)100663296)
#define OFF_AB   ((size_t)106954752)
#define OFF_CIN  ((size_t)108003328)

#define WSEG_H ((size_t)2097152)   // halfs per weight matrix

// ---------------------------------------------------------------------------
// helpers
// ---------------------------------------------------------------------------
__device__ __forceinline__ float sigmoidf_(float x) {
    return 1.0f / (1.0f + expf(-x));
}
__device__ __forceinline__ void cp16(void* dst, const void* src) {
    uint32_t d = (uint32_t)__cvta_generic_to_shared(dst);
    asm volatile("cp.async.cg.shared.global [%0], [%1], 16;\n" :: "r"(d), "l"(src));
}

// k-permuted fp16 storage: within each 16-k block, pair order
// [0,1,8,9,2,3,10,11,4,5,12,13,6,7,14,15]. psl(k) for even k gives the stored
// index of that pair's first element (odd partner is psl(k)+1).
__device__ __forceinline__ int psl(int k) {
    const int p = (k >> 1) & 7;
    return (k & ~15) | ((((p & 3) << 1) | (p >> 2)) << 1);
}

__device__ __forceinline__ void mma_f16(float4& c, uint32_t a0, uint32_t a1,
                                        uint32_t a2, uint32_t a3,
                                        uint32_t b0, uint32_t b1) {
    asm volatile(
        "mma.sync.aligned.m16n8k16.row.col.f32.f16.f16.f32 "
        "{%0,%1,%2,%3}, {%4,%5,%6,%7}, {%8,%9}, {%0,%1,%2,%3};\n"
        : "+f"(c.x), "+f"(c.y), "+f"(c.z), "+f"(c.w)
        : "r"(a0), "r"(a1), "r"(a2), "r"(a3), "r"(b0), "r"(b1));
}

// ---------------------------------------------------------------------------
// Fused: rmsnorm of x (blocks [0, Mrows)) + weight fp16-permute prep
// (blocks [Mrows, Mrows+12288)). Removes one serialized launch.
// ---------------------------------------------------------------------------
__global__ void __launch_bounds__(256) norm1_prep(
    const float* __restrict__ x, const float* __restrict__ g,
    __half* __restrict__ outx,
    const float* __restrict__ w0, const float* __restrict__ w1,
    const float* __restrict__ w2, const float* __restrict__ w3,
    const float* __restrict__ w4, const float* __restrict__ w5,
    __half* __restrict__ wdst)
{
    const int t = threadIdx.x;
    if (blockIdx.x < Mrows) {
        const int row = blockIdx.x;
        const float4* xr = reinterpret_cast<const float4*>(x) + (size_t)row * (Dc / 4);
        float4 v = xr[t];
        float ss = v.x * v.x + v.y * v.y + v.z * v.z + v.w * v.w;
        #pragma unroll
        for (int off = 16; off > 0; off >>= 1)
            ss += __shfl_down_sync(0xffffffffu, ss, off);
        __shared__ float warp_s[8];
        if ((t & 31) == 0) warp_s[t >> 5] = ss;
        __syncthreads();
        float tot = 0.f;
        #pragma unroll
        for (int i = 0; i < 8; i++) tot += warp_s[i];
        const float scale = rsqrtf(tot * (1.0f / Dc) + 1e-6f);
        float4 gv = reinterpret_cast<const float4*>(g)[t];
        __half* d = outx + (size_t)row * Dc;
        const int k = 4 * t;
        *reinterpret_cast<__half2*>(d + psl(k)) =
            __floats2half2_rn(v.x * scale * gv.x, v.y * scale * gv.y);
        *reinterpret_cast<__half2*>(d + psl(k + 2)) =
            __floats2half2_rn(v.z * scale * gv.z, v.w * scale * gv.w);
    } else {
        const size_t i4 = (size_t)(blockIdx.x - Mrows) * 256 + t;
        const int seg = (int)(i4 >> 19);            // 524288 float4 per matrix
        const size_t off = (i4 & 524287) * 4;
        const float* src;
        switch (seg) {
            case 0: src = w0; break; case 1: src = w1; break;
            case 2: src = w2; break; case 3: src = w3; break;
            case 4: src = w4; break; default: src = w5; break;
        }
        float4 v = *reinterpret_cast<const float4*>(src + off);
        __half* d = wdst + seg * WSEG_H + (off & ~(size_t)15);
        const int j = (int)(off & 15);
        *reinterpret_cast<__half2*>(d + (psl(j) & 15))     = __floats2half2_rn(v.x, v.y);
        *reinterpret_cast<__half2*>(d + (psl(j + 2) & 15)) = __floats2half2_rn(v.z, v.w);
    }
}

// ---------------------------------------------------------------------------
// RMSNorm: fp32 in -> k-permuted fp16 out (used for norm2)
// ---------------------------------------------------------------------------
__global__ void __launch_bounds__(256) rmsnorm_kernel(
    const float* __restrict__ x, const float* __restrict__ g,
    __half* __restrict__ out)
{
    const int row = blockIdx.x;
    const int t = threadIdx.x;
    const float4* xr = reinterpret_cast<const float4*>(x) + (size_t)row * (Dc / 4);
    float4 v = xr[t];
    float ss = v.x * v.x + v.y * v.y + v.z * v.z + v.w * v.w;
    #pragma unroll
    for (int off = 16; off > 0; off >>= 1)
        ss += __shfl_down_sync(0xffffffffu, ss, off);
    __shared__ float warp_s[8];
    if ((t & 31) == 0) warp_s[t >> 5] = ss;
    __syncthreads();
    float tot = 0.f;
    #pragma unroll
    for (int i = 0; i < 8; i++) tot += warp_s[i];
    const float scale = rsqrtf(tot * (1.0f / Dc) + 1e-6f);
    float4 gv = reinterpret_cast<const float4*>(g)[t];
    __half* d = out + (size_t)row * Dc;
    const int k = 4 * t;
    *reinterpret_cast<__half2*>(d + psl(k)) =
        __floats2half2_rn(v.x * scale * gv.x, v.y * scale * gv.y);
    *reinterpret_cast<__half2*>(d + psl(k + 2)) =
        __floats2half2_rn(v.z * scale * gv.z, v.w * scale * gv.w);
}

// ---------------------------------------------------------------------------
// fp16 HMMA GEMM: C[M,N] = epilogue(A[M,K] @ W[N,K]^T)
// A, W are k-permuted fp16. BM=128, BN=64, BK=32, 256 threads
// (8 warps: 4m x 2n), warp tile 32x32, m16n8k16 HMMA, fp32 accumulate.
// 3-stage cp.async pipeline; smem row stride 96 B -> conflict-free LDS.64.
// MODE 0: dual -> rem fp16 / ri fp16 planes (quantize-then-aggregate), PLUS
//         fused per-chunk (A,S) scan aggregates to AB (tile = 2 chunks).
// MODE 1: dual -> FF = fp16 permuted( z1 * silu(z2) )
// MODE 2: single -> fp32 z1 + bias + residual
// ---------------------------------------------------------------------------
template <int MODE>
__global__ void __launch_bounds__(256, 2) gemm_f16(
    const __half* __restrict__ A,
    const __half* __restrict__ W1,
    const __half* __restrict__ W2,
    const float* __restrict__ b1,
    const float* __restrict__ b2,
    const float* __restrict__ res,
    float* __restrict__ out,         // MODE1: __half* FF; MODE2: fp32 out
    __half* __restrict__ rem_p,      // MODE0: remember plane
    __half* __restrict__ ri_p,       // MODE0: ri plane
    float2* __restrict__ ab,         // MODE0: chunk aggregates
    int M, int N, int K)
{
    constexpr bool DUAL = (MODE != 2);
    constexpr int STAGEB = DUAL ? 24576 : 18432;  // bytes per stage
    extern __shared__ char sm[];

    const int tid  = threadIdx.x;
    const int lane = tid & 31;
    const int wid  = tid >> 5;
    const int wm = wid >> 1;           // 0..3
    const int wn = wid & 1;            // 0..1
    const int gid = lane >> 2;         // 0..7
    const int tig = lane & 3;          // 0..3
    const int bm = blockIdx.y * 128;
    const int bn = blockIdx.x * 64;
    const int niter = K >> 5;

    float4 acc1[2][4];
    float4 acc2[2][4];
    #pragma unroll
    for (int i = 0; i < 2; i++)
        #pragma unroll
        for (int j = 0; j < 4; j++) {
            acc1[i][j] = make_float4(0.f, 0.f, 0.f, 0.f);
            acc2[i][j] = make_float4(0.f, 0.f, 0.f, 0.f);
        }

    auto load_stage = [&](int slot, int it) {
        char* st = sm + slot * STAGEB;
        const int k0 = it << 5;
        #pragma unroll
        for (int i = 0; i < 2; i++) {
            int q = tid + (i << 8);
            int r = q >> 2, c = q & 3;
            cp16(st + r * 96 + c * 16, A + (size_t)(bm + r) * K + k0 + c * 8);
        }
        {
            int r = tid >> 2, c = tid & 3;
            cp16(st + 12288 + r * 96 + c * 16,
                 W1 + (size_t)(bn + r) * K + k0 + c * 8);
            if (DUAL)
                cp16(st + 18432 + r * 96 + c * 16,
                     W2 + (size_t)(bn + r) * K + k0 + c * 8);
        }
    };

    load_stage(0, 0);
    asm volatile("cp.async.commit_group;\n");
    load_stage(1, 1);
    asm volatile("cp.async.commit_group;\n");

    int slot = 0;
    for (int it = 0; it < niter; ++it) {
        if (it + 2 < niter)
            load_stage((it + 2) % 3, it + 2);
        asm volatile("cp.async.commit_group;\n");
        asm volatile("cp.async.wait_group 2;\n");
        __syncthreads();

        const char* st = sm + slot * STAGEB;
        const __half* As = reinterpret_cast<const __half*>(st);
        const __half* B1s = reinterpret_cast<const __half*>(st + 12288);
        const __half* B2s = reinterpret_cast<const __half*>(st + 18432);

        #pragma unroll
        for (int ks = 0; ks < 2; ks++) {
            const int ko = ks * 16 + 4 * tig;
            uint2 alo[2], ahi[2];
            #pragma unroll
            for (int mf = 0; mf < 2; mf++) {
                const int r = wm * 32 + mf * 16 + gid;
                alo[mf] = *reinterpret_cast<const uint2*>(As + r * 48 + ko);
                ahi[mf] = *reinterpret_cast<const uint2*>(As + (r + 8) * 48 + ko);
            }
            #pragma unroll
            for (int nf = 0; nf < 4; nf++) {
                const int n = wn * 32 + nf * 8 + gid;
                const uint2 bv = *reinterpret_cast<const uint2*>(B1s + n * 48 + ko);
                uint2 cv;
                if (DUAL) cv = *reinterpret_cast<const uint2*>(B2s + n * 48 + ko);
                #pragma unroll
                for (int mf = 0; mf < 2; mf++) {
                    mma_f16(acc1[mf][nf], alo[mf].x, ahi[mf].x, alo[mf].y, ahi[mf].y,
                            bv.x, bv.y);
                    if (DUAL)
                        mma_f16(acc2[mf][nf], alo[mf].x, ahi[mf].x, alo[mf].y, ahi[mf].y,
                                cv.x, cv.y);
                }
            }
        }
        __syncthreads();
        slot = (slot + 1 == 3) ? 0 : slot + 1;
    }

    // ------------------------------ Epilogue ------------------------------
    // MODE0 staging for the fused chunk-scan: float2 (f, ri) per cell,
    // row stride 65 float2 -> 66560 B <= 73728 B pipeline smem.
    float2* stg = reinterpret_cast<float2*>(sm);

    #pragma unroll
    for (int nf = 0; nf < 4; nf++) {
        const int cl0 = wn * 32 + nf * 8 + 2 * tig;       // local col (even)
        const int c0 = bn + cl0;
        const float bias1a = b1[c0], bias1b = b1[c0 + 1];
        float bias2a = 0.f, bias2b = 0.f;
        if (DUAL) { bias2a = b2[c0]; bias2b = b2[c0 + 1]; }
        float decaya = 0.f, decayb = 0.f;
        if (MODE == 0) {
            const float inv = 1.0f / (float)(N - 1);
            decaya = (float)c0 * inv;
            decayb = (float)(c0 + 1) * inv;
        }
        #pragma unroll
        for (int mf = 0; mf < 2; mf++) {
            const float4 a1 = acc1[mf][nf];
            const float4 a2 = acc2[mf][nf];
            #pragma unroll
            for (int h = 0; h < 2; h++) {
                const int rl = wm * 32 + mf * 16 + gid + h * 8;   // local row
                const int r = bm + rl;
                const float z1a = (h ? a1.z : a1.x) + bias1a;
                const float z1b = (h ? a1.w : a1.y) + bias1b;
                if (MODE == 0) {
                    const float z2a = (h ? a2.z : a2.x) + bias2a;
                    const float z2b = (h ? a2.w : a2.y) + bias2b;
                    const float rema = decaya * sigmoidf_(z1a);
                    const float remb = decayb * sigmoidf_(z1b);
                    const float ria = rema * tanhf(z2a);
                    const float rib = remb * tanhf(z2b);
                    // quantize FIRST so aggregates match scan_apply exactly
                    const __half2 rem_h = __floats2half2_rn(rema, remb);
                    const __half2 ri_h  = __floats2half2_rn(ria, rib);
                    const size_t idx = (size_t)r * N + c0;
                    *reinterpret_cast<__half2*>(rem_p + idx) = rem_h;
                    *reinterpret_cast<__half2*>(ri_p + idx)  = ri_h;
                    const float2 rem_q = __half22float2(rem_h);
                    const float2 ri_q  = __half22float2(ri_h);
                    stg[rl * 65 + cl0]     = make_float2(1.0f - rem_q.x, ri_q.x);
                    stg[rl * 65 + cl0 + 1] = make_float2(1.0f - rem_q.y, ri_q.y);
                } else if (MODE == 1) {
                    const float z2a = (h ? a2.z : a2.x) + bias2a;
                    const float z2b = (h ? a2.w : a2.y) + bias2b;
                    const float va = z1a * (z2a * sigmoidf_(z2a));
                    const float vb = z1b * (z2b * sigmoidf_(z2b));
                    __half* fo = reinterpret_cast<__half*>(out) + (size_t)r * N;
                    *reinterpret_cast<__half2*>(fo + psl(c0)) = __floats2half2_rn(va, vb);
                } else {
                    const size_t idx = (size_t)r * N + c0;
                    const float2 rv = *reinterpret_cast<const float2*>(res + idx);
                    float2 o;
                    o.x = z1a + rv.x;
                    o.y = z1b + rv.y;
                    *reinterpret_cast<float2*>(out + idx) = o;
                }
            }
        }
    }

    if (MODE == 0) {
        // Fused chunk-scan: 128 chains (2 chunks x 64 cols), 64 steps each.
        __syncthreads();
        if (tid < 128) {
            const int chunk = tid >> 6;      // 0..1
            const int col = tid & 63;        // 0..63
            const float2* p = stg + (chunk * 64) * 65 + col;
            float a = 1.0f, s = 0.0f;
            #pragma unroll 8
            for (int rr = 0; rr < 64; rr++) {
                const float2 v = p[rr * 65];
                s = fmaf(v.x, s, v.y);
                a *= v.x;
            }
            const int b = bm >> 12;                       // bm / 4096
            const int cglob = ((bm & 4095) >> 6) + chunk; // chunk index in b
            ab[((size_t)(b * 64 + cglob) << 11) + bn + col] = make_float2(a, s);
        }
    }
    (void)M;
}

// ---------------------------------------------------------------------------
// Cross-chunk carry: one thread per channel, 8-wide batched AB prefetch.
// ---------------------------------------------------------------------------
__global__ void __launch_bounds__(256) scan_carry(
    const float2* __restrict__ ab,
    const float* __restrict__ hidden,
    float* __restrict__ cin,
    float* __restrict__ hlast)
{
    const int idx = blockIdx.x * 256 + threadIdx.x;   // 0 .. B*H-1
    const int b = idx >> 11;
    const int h = idx & (Hc - 1);
    float carry = hidden[idx];
    const float2* pab = ab + ((size_t)(b * 64) << 11) + h;
    float* pc = cin + ((size_t)(b * 64) << 11) + h;
    for (int c0 = 0; c0 < 64; c0 += 8) {
        float2 v[8];
        #pragma unroll
        for (int u = 0; u < 8; u++) v[u] = pab[(size_t)(c0 + u) << 11];
        #pragma unroll
        for (int u = 0; u < 8; u++) {
            pc[(size_t)(c0 + u) << 11] = carry;
            carry = fmaf(v[u].x, carry, v[u].y);
        }
    }
    hlast[idx] = carry;
}

// ---------------------------------------------------------------------------
// Re-apply with correct carry-in; channel pairs; f = 1 - rem (fp32 exact).
// HBUF written k-permuted fp16.
// ---------------------------------------------------------------------------
__global__ void __launch_bounds__(256) scan_apply(
    const __half2* __restrict__ rem2,
    const __half2* __restrict__ rip2,
    const float2* __restrict__ cin2,
    __half2* __restrict__ hbuf2)
{
    const int idx = blockIdx.x * 256 + threadIdx.x;   // B*64*1024 pairs
    const int hp = idx & 1023;
    const int rest = idx >> 10;
    const int c = rest & 63;
    const int b = rest >> 6;
    const size_t offp = ((size_t)b * Lc + (size_t)c * 64) * (Hc / 2);  // in pairs
    const __half2* pm = rem2 + offp + hp;
    const __half2* pr = rip2 + offp + hp;
    __half2* o = hbuf2 + offp + (psl(2 * hp) >> 1);
    float2 carry = cin2[idx];
    for (int t = 0; t < 64; t += 8) {
        __half2 m[8], r[8];
        #pragma unroll
        for (int u = 0; u < 8; u++) {
            m[u] = pm[(size_t)(t + u) * (Hc / 2)];
            r[u] = pr[(size_t)(t + u) * (Hc / 2)];
        }
        #pragma unroll
        for (int u = 0; u < 8; u++) {
            const float2 mv = __half22float2(m[u]);
            const float2 rv = __half22float2(r[u]);
            carry.x = fmaf(1.0f - mv.x, carry.x, rv.x);
            carry.y = fmaf(1.0f - mv.y, carry.y, rv.y);
            o[(size_t)(t + u) * (Hc / 2)] = __floats2half2_rn(carry.x, carry.y);
        }
    }
}

// ---------------------------------------------------------------------------
// kernel_launch
// ---------------------------------------------------------------------------
extern "C" void kernel_launch(void* const* d_in, const int* in_sizes, int n_in,
                              void* d_out, int out_size)
{
    const float* x        = (const float*)d_in[0];
    const float* hidden   = (const float*)d_in[1];
    const float* w_forget = (const float*)d_in[2];
    const float* b_forget = (const float*)d_in[3];
    const float* w_input  = (const float*)d_in[4];
    const float* b_input  = (const float*)d_in[5];
    const float* w_hout   = (const float*)d_in[6];
    const float* b_hout   = (const float*)d_in[7];
    const float* w_fc     = (const float*)d_in[8];
    const float* b_fc     = (const float*)d_in[9];
    const float* w_fc_act = (const float*)d_in[10];
    const float* b_fc_act = (const float*)d_in[11];
    const float* w_fout   = (const float*)d_in[12];
    const float* b_fout   = (const float*)d_in[13];
    const float* g_norm1  = (const float*)d_in[14];
    const float* g_norm2  = (const float*)d_in[15];
    float* out = (float*)d_out;

    float* gbuf = nullptr;
    cudaGetSymbolAddress((void**)&gbuf, g_buf);
    __half* REMp = (__half*)(gbuf + OFF_REMP);
    __half* RIp  = (__half*)(gbuf + OFF_RIP);
    __half* HBUF = (__half*)(gbuf + OFF_HBUF);
    float*  X1   = gbuf + OFF_X1;
    __half* XN   = (__half*)(gbuf + OFF_XN);
    __half* XN2  = (__half*)(gbuf + OFF_XN2);
    __half* FF   = (__half*)(gbuf + OFF_FF);
    __half* WT   = (__half*)(gbuf + OFF_WT);
    float*  AB   = gbuf + OFF_AB;
    float*  CIN  = gbuf + OFF_CIN;

    const int smem_dual   = 3 * 24576;  // 73728
    const int smem_single = 3 * 18432;  // 55296
    static bool attr_done = false;
    if (!attr_done) {
        cudaFuncSetAttribute(gemm_f16<0>, cudaFuncAttributeMaxDynamicSharedMemorySize, smem_dual);
        cudaFuncSetAttribute(gemm_f16<1>, cudaFuncAttributeMaxDynamicSharedMemorySize, smem_dual);
        cudaFuncSetAttribute(gemm_f16<2>, cudaFuncAttributeMaxDynamicSharedMemorySize, smem_single);
        attr_done = true;
    }

    const __half* Wf   = WT + 0 * WSEG_H;
    const __half* Wi   = WT + 1 * WSEG_H;
    const __half* Who  = WT + 2 * WSEG_H;
    const __half* Wfc  = WT + 3 * WSEG_H;
    const __half* Wfca = WT + 4 * WSEG_H;
    const __half* Wfo  = WT + 5 * WSEG_H;

    // 0+1. fused: xn = fp16(rmsnorm(x)*g1)  AND  weight fp16-permute prep
    norm1_prep<<<Mrows + 12288, 256>>>(
        x, g_norm1, XN,
        w_forget, w_input, w_hout, w_fc, w_fc_act, w_fout, WT);

    // 2. dual GEMM -> (rem fp16, ri fp16) + fused chunk aggregates
    gemm_f16<0><<<dim3(Hc / 64, Mrows / 128), 256, smem_dual>>>(
        XN, Wf, Wi, b_forget, b_input, nullptr, nullptr, REMp, RIp, (float2*)AB,
        Mrows, Hc, Dc);

    // 3. carry across chunks (h_last -> output tail), then re-apply
    scan_carry<<<(Bc * Hc) / 256, 256>>>(
        (const float2*)AB, hidden, CIN, out + BLD);
    scan_apply<<<(Bc * 64 * Hc / 2) / 256, 256>>>(
        (const __half2*)REMp, (const __half2*)RIp, (const float2*)CIN,
        (__half2*)HBUF);

    // 4. x1 = h @ w_hout^T + b_hout + x      (fp32 out)
    gemm_f16<2><<<dim3(Dc / 64, Mrows / 128), 256, smem_single>>>(
        HBUF, Who, nullptr, b_hout, nullptr, x, X1, nullptr, nullptr, nullptr,
        Mrows, Dc, Hc);

    // 5. xn2 = fp16(rmsnorm(x1) * g2), k-permuted
    rmsnorm_kernel<<<Mrows, 256>>>(X1, g_norm2, XN2);

    // 6. dual GEMM -> ff = fc * silu(fc_act)  (fp16 permuted out)
    gemm_f16<1><<<dim3(Hc / 64, Mrows / 128), 256, smem_dual>>>(
        XN2, Wfc, Wfca, b_fc, b_fc_act, nullptr, (float*)FF, nullptr, nullptr, nullptr,
        Mrows, Hc, Dc);

    // 7. out = ff @ w_fout^T + b_fout + x1   (fp32 out)
    gemm_f16<2><<<dim3(Dc / 64, Mrows / 128), 256, smem_single>>>(
        FF, Wfo, nullptr, b_fout, nullptr, X1, out, nullptr, nullptr, nullptr,
        Mrows, Dc, Hc);

    (void)in_sizes; (void)n_in; (void)out_size;
}